// round 9
// baseline (speedup 1.0000x reference)
#include <cuda_runtime.h>
#include <cuda_bf16.h>
#include <math.h>
#include <stdint.h>

#define RES   4096
#define DD    128
#define NN    256
#define BB    8
#define SS    256
#define VV    50257
#define LL    2
#define WROWS 50304          // 393 * 128, padded vocab rows
#define NTILES 393
#define MTILES 16
#define UNITS  (NTILES * MTILES)   // 6288
#define CHUNKS 444                 // 148 * 3 -> exactly 3 waves

// Constants matching the reference's fp32 casts of python doubles
#define PHIF   ((float)1.6180339887498948482045868343656381177203)
#define STEPF  ((float)(6.2831853071795864769252867665590 / 4096.0))
#define SCALEF ((float)(4096.0 / 6.2831853071795864769252867665590))

// Scratch (no allocation allowed)
__device__ float g_sin[RES];
__device__ float g_cos[RES];
__device__ float g_X[SS * BB * DD];   // rows m = t*8 + b, 128 cols

// Pre-split bf16 hi/lo planes (row-major: row*128 bf16 = 256B rows)
__device__ __align__(16) __nv_bfloat16 g_Wh[WROWS * DD];
__device__ __align__(16) __nv_bfloat16 g_Wl[WROWS * DD];
__device__ __align__(16) __nv_bfloat16 g_Xh[SS * BB * DD];
__device__ __align__(16) __nv_bfloat16 g_Xl[SS * BB * DD];

// ===========================================================================
// Helpers
// ===========================================================================
__device__ __forceinline__ uint32_t smem_u32(const void* p) {
    uint32_t a;
    asm("{ .reg .u64 t; cvta.to.shared.u64 t, %1; cvt.u32.u64 %0, t; }"
        : "=r"(a) : "l"(p));
    return a;
}

__device__ __forceinline__ uint32_t pk(__nv_bfloat16 a, __nv_bfloat16 b) {
    uint16_t ua = *(uint16_t*)&a, ub = *(uint16_t*)&b;
    return (uint32_t)ua | ((uint32_t)ub << 16);
}

#define LDMATRIX_X4(r0, r1, r2, r3, addr)                                     \
    asm volatile("ldmatrix.sync.aligned.m8n8.x4.shared.b16 {%0,%1,%2,%3}, [%4];" \
        : "=r"(r0), "=r"(r1), "=r"(r2), "=r"(r3) : "r"(addr))

#define MMA_BF16(c, a0, a1, a2, a3, b0, b1)                                   \
    asm volatile("mma.sync.aligned.m16n8k16.row.col.f32.bf16.bf16.f32 "       \
        "{%0,%1,%2,%3}, {%4,%5,%6,%7}, {%8,%9}, {%0,%1,%2,%3};"               \
        : "+f"((c)[0]), "+f"((c)[1]), "+f"((c)[2]), "+f"((c)[3])              \
        : "r"(a0), "r"(a1), "r"(a2), "r"(a3), "r"(b0), "r"(b1))

#define CP_ASYNC16(smaddr, gptr)                                              \
    asm volatile("cp.async.cg.shared.global [%0], [%1], 16;"                  \
        :: "r"(smaddr), "l"(gptr))
#define CP_COMMIT() asm volatile("cp.async.commit_group;" ::: "memory")
#define CP_WAIT0()  asm volatile("cp.async.wait_group 0;" ::: "memory")
#define CP_WAIT1()  asm volatile("cp.async.wait_group 1;" ::: "memory")

// ---------------------------------------------------------------------------
// Kernel 0: build sin/cos tables exactly like the reference
// ---------------------------------------------------------------------------
__global__ void k_tables() {
    int i = blockIdx.x * blockDim.x + threadIdx.x;
    if (i < RES) {
        float a = __fmul_rn((float)i, STEPF);
        g_sin[i] = sinf(a);
        g_cos[i] = cosf(a);
    }
}

// ---------------------------------------------------------------------------
// Kernel 1: elementwise recurrence over t (bit-exact path, unchanged)
// ---------------------------------------------------------------------------
__global__ void k_recur(const int* __restrict__ ids,
                        const float* __restrict__ emb,
                        float* __restrict__ out) {
    __shared__ float s_sin[RES];
    __shared__ float s_cos[RES];
    __shared__ int   s_ids[SS];

    int b = blockIdx.x;
    int d = threadIdx.x;   // 128 threads

    for (int i = d; i < RES; i += 128) { s_sin[i] = g_sin[i]; s_cos[i] = g_cos[i]; }
    for (int i = d; i < SS;  i += 128) s_ids[i] = ids[b * SS + i];
    __syncthreads();

    float hr = 0.0f, hi = 0.0f;

    for (int t0 = 0; t0 < SS; t0 += 8) {
        float wv[8], bv[8];
#pragma unroll
        for (int j = 0; j < 8; ++j) {
            const float* e = emb + (size_t)s_ids[t0 + j] * (2 * DD);
            wv[j] = e[d];
            bv[j] = e[DD + d];
        }
#pragma unroll
        for (int j = 0; j < 8; ++j) {
            int   t     = t0 + j;
            float tphi  = __fmul_rn((float)t, PHIF);
            float num   = __fadd_rn(hr, hi);
            float den   = __fadd_rn(1.0f, fabsf(wv[j]));
            float theta = __fadd_rn(__fadd_rn(__fdiv_rn(num, den), bv[j]), tphi);
            int   idx   = __float2int_rn(__fmul_rn(theta, SCALEF)) & (RES - 1);
            hi = s_sin[idx];
            hr = s_cos[idx];
            g_X[(size_t)t * (BB * DD) + b * DD + d] = __fadd_rn(hr, hi);
        }
    }

    size_t base = (size_t)BB * SS * VV;
    out[base + b * DD + d]            = hr;  // h_real
    out[base + BB * DD + b * DD + d]  = hi;  // h_imag
}

// ---------------------------------------------------------------------------
// Kernel 2: the two MLP layers — 512 threads/block for halved phase latency.
// Phase A: thread (n = tid&255, bh = tid>>8) computes th[b][n] for 4 b's.
// Phase B: thread (dcol = tid&127, bq = tid>>7) computes o for b = bq, bq+4.
// ---------------------------------------------------------------------------
__global__ void __launch_bounds__(512)
k_layers(const float* __restrict__ W,
         const float* __restrict__ bias,
         const float* __restrict__ Wr,
         const float* __restrict__ Wi) {
    extern __shared__ float sm[];
    float* s_sin = sm;                  // 4096
    float* s_cos = s_sin + RES;         // 4096
    float* s_x   = s_cos + RES;         // 1024  (8 x 128)
    float* s_cs  = s_x + BB * DD;       // 2048  (8 x 256)
    float* s_sn  = s_cs + BB * NN;      // 2048
    float* s_wr  = s_sn + BB * NN;      // 128*36
    float* s_wi  = s_wr + DD * 36;      // 128*36

    int tid = threadIdx.x;
    int t   = blockIdx.x;

    for (int i = tid; i < RES; i += 512) { s_sin[i] = g_sin[i]; s_cos[i] = g_cos[i]; }
    float* gx = g_X + (size_t)t * (BB * DD);
    for (int i = tid; i < BB * DD; i += 512) s_x[i] = gx[i];
    __syncthreads();

    float tphi = __fmul_rn((float)t, PHIF);
    int n    = tid & 255;
    int bh   = tid >> 8;     // 0/1 -> handles b = 4*bh .. 4*bh+3 in Phase A
    int dcol = tid & 127;
    int bq   = (tid >> 7) & 3;   // 0..3 -> handles b = bq, bq+4 in Phase B

    for (int layer = 0; layer < LL; ++layer) {
        // ---- Phase A: th = x @ W^T + b + tphi -> table lookups
        const float4* Wn = (const float4*)(W + ((size_t)layer * NN + n) * DD);
        const float4* x4 = (const float4*)s_x;
        float acc[4];
#pragma unroll
        for (int j = 0; j < 4; ++j) acc[j] = 0.0f;
#pragma unroll 8
        for (int q = 0; q < 32; ++q) {
            float4 w = Wn[q];
#pragma unroll
            for (int j = 0; j < 4; ++j) {
                float4 xv = x4[(4 * bh + j) * 32 + q];
                acc[j] += w.x * xv.x + w.y * xv.y + w.z * xv.z + w.w * xv.w;
            }
        }
        float bsn = bias[layer * NN + n];
#pragma unroll
        for (int j = 0; j < 4; ++j) {
            int   bb  = 4 * bh + j;
            float th  = acc[j] + bsn + tphi;
            int   idx = __float2int_rn(__fmul_rn(th, SCALEF)) & (RES - 1);
            s_sn[bb * NN + n] = s_sin[idx];
            s_cs[bb * NN + n] = s_cos[idx];
        }
        __syncthreads();

        // ---- Phase B: o[b][d] = cs @ Wr^T + sn @ Wi^T (tile over n)
        float o[2] = {0.0f, 0.0f};
        const float* WrL = Wr + (size_t)layer * DD * NN;
        const float* WiL = Wi + (size_t)layer * DD * NN;
        for (int n0 = 0; n0 < NN; n0 += 32) {
#pragma unroll
            for (int l2 = 0; l2 < 8; ++l2) {
                int f  = tid + 512 * l2;   // 0..4095
                int dd = f >> 5, nn2 = f & 31;
                s_wr[dd * 36 + nn2] = WrL[dd * NN + n0 + nn2];
                s_wi[dd * 36 + nn2] = WiL[dd * NN + n0 + nn2];
            }
            __syncthreads();
            const float4* wr4 = (const float4*)(s_wr + dcol * 36);
            const float4* wi4 = (const float4*)(s_wi + dcol * 36);
#pragma unroll
            for (int q = 0; q < 8; ++q) {
                float4 wr = wr4[q];
                float4 wi = wi4[q];
#pragma unroll
                for (int p = 0; p < 2; ++p) {
                    int bb = bq + 4 * p;
                    float4 cs = ((const float4*)(s_cs + bb * NN + n0))[q];
                    float4 sn = ((const float4*)(s_sn + bb * NN + n0))[q];
                    o[p] += cs.x * wr.x + cs.y * wr.y + cs.z * wr.z + cs.w * wr.w
                          + sn.x * wi.x + sn.y * wi.y + sn.z * wi.z + sn.w * wi.w;
                }
            }
            __syncthreads();
        }
#pragma unroll
        for (int p = 0; p < 2; ++p) {
            int bb = bq + 4 * p;
            float ov = o[p];
            float sv = ov / (1.0f + expf(-ov));   // o * sigmoid(o)
            s_x[bb * DD + dcol] += sv;
        }
        __syncthreads();
    }

    for (int i = tid; i < BB * DD; i += 512) gx[i] = s_x[i];
}

// ---------------------------------------------------------------------------
// Split kernels: fp32 -> bf16 hi/lo planes, row-major (cp.async-ready).
// ---------------------------------------------------------------------------
__device__ __forceinline__ void split4(float4 v, uint2& hp, uint2& lp) {
    __nv_bfloat16 h0 = __float2bfloat16(v.x);
    __nv_bfloat16 h1 = __float2bfloat16(v.y);
    __nv_bfloat16 h2 = __float2bfloat16(v.z);
    __nv_bfloat16 h3 = __float2bfloat16(v.w);
    __nv_bfloat16 l0 = __float2bfloat16(v.x - __bfloat162float(h0));
    __nv_bfloat16 l1 = __float2bfloat16(v.y - __bfloat162float(h1));
    __nv_bfloat16 l2 = __float2bfloat16(v.z - __bfloat162float(h2));
    __nv_bfloat16 l3 = __float2bfloat16(v.w - __bfloat162float(h3));
    hp = make_uint2(pk(h0, h1), pk(h2, h3));
    lp = make_uint2(pk(l0, l1), pk(l2, l3));
}

__global__ void k_split_w(const float* __restrict__ Wv) {
    int f = blockIdx.x * blockDim.x + threadIdx.x;   // 0 .. WROWS*32-1
    int r = f >> 5, kq = f & 31;
    float4 v = make_float4(0.f, 0.f, 0.f, 0.f);
    if (r < VV) v = ((const float4*)Wv)[(size_t)r * 32 + kq];
    uint2 hp, lp;
    split4(v, hp, lp);
    ((uint2*)g_Wh)[f] = hp;
    ((uint2*)g_Wl)[f] = lp;
}

__global__ void k_split_x() {
    int f = blockIdx.x * blockDim.x + threadIdx.x;   // 0 .. 2048*32-1
    float4 v = ((const float4*)g_X)[f];
    uint2 hp, lp;
    split4(v, hp, lp);
    ((uint2*)g_Xh)[f] = hp;
    ((uint2*)g_Xl)[f] = lp;
}

// ---------------------------------------------------------------------------
// Kernel 3: work-list logits GEMM. 444 CTAs (exactly 3 waves) each process a
// contiguous chunk of the 6288 (nt, mt) units, n-major so B stays in smem
// across up to 16 consecutive units. A double-buffered via cp.async; all 32
// fragment regs double-buffered across k16 so LDSM overlaps MMA.
// smem: BH 32K | BL 32K | A0(H,L) 64K | A1(H,L) 64K = 192KB
// ---------------------------------------------------------------------------
#define PB_BH 0u
#define PB_BL 32768u
#define PB_A0 65536u
#define PB_A1 131072u
#define SMEM_PIPE 196608u

__device__ __forceinline__ void issue_B(uint32_t sb, int nt, int tid) {
    const char* gWh = (const char*)g_Wh;
    const char* gWl = (const char*)g_Wl;
#pragma unroll
    for (int i = 0; i < 4; ++i) {
        int f = tid + 512 * i;            // 0..2047
        int r = f >> 4, u = f & 15;
        uint32_t so = (uint32_t)(r * 256 + ((u ^ (r & 7)) << 4));
        size_t   go = (size_t)(nt * 128 + r) * 256 + u * 16;
        CP_ASYNC16(sb + PB_BH + so, gWh + go);
        CP_ASYNC16(sb + PB_BL + so, gWl + go);
    }
}

__device__ __forceinline__ void issue_A(uint32_t sb, uint32_t bufoff, int mt, int tid) {
    const char* gXh = (const char*)g_Xh;
    const char* gXl = (const char*)g_Xl;
#pragma unroll
    for (int i = 0; i < 4; ++i) {
        int f = tid + 512 * i;
        int r = f >> 4, u = f & 15;
        uint32_t so = (uint32_t)(r * 256 + ((u ^ (r & 7)) << 4));
        size_t   go = (size_t)(mt * 128 + r) * 256 + u * 16;
        CP_ASYNC16(sb + bufoff + so, gXh + go);
        CP_ASYNC16(sb + bufoff + 32768u + so, gXl + go);
    }
}

// fragment layout: [0..7]=aH(mf0,mf1), [8..15]=bH(nf0..3), [16..23]=bL, [24..31]=aL
__device__ __forceinline__ void load_frags(uint32_t* fr, uint32_t abase,
                                           const uint32_t* arel, const uint32_t* brow,
                                           uint32_t uxa, uint32_t uxb) {
    LDMATRIX_X4(fr[0],  fr[1],  fr[2],  fr[3],  abase + arel[0] + uxa);
    LDMATRIX_X4(fr[4],  fr[5],  fr[6],  fr[7],  abase + arel[1] + uxa);
    LDMATRIX_X4(fr[8],  fr[9],  fr[10], fr[11], brow[0] + uxb);
    LDMATRIX_X4(fr[12], fr[13], fr[14], fr[15], brow[1] + uxb);
    LDMATRIX_X4(fr[16], fr[17], fr[18], fr[19], brow[0] + 32768u + uxb);
    LDMATRIX_X4(fr[20], fr[21], fr[22], fr[23], brow[1] + 32768u + uxb);
    LDMATRIX_X4(fr[24], fr[25], fr[26], fr[27], abase + 32768u + arel[0] + uxa);
    LDMATRIX_X4(fr[28], fr[29], fr[30], fr[31], abase + 32768u + arel[1] + uxa);
}

__global__ void __launch_bounds__(512, 1)
k_logits_wl(float* __restrict__ out) {
    extern __shared__ char smc[];
    uint32_t sb = smem_u32(smc);

    int tid  = threadIdx.x;
    int lane = tid & 31;
    int wid  = tid >> 5;
    int cid  = blockIdx.x;

    int start = (cid * UNITS) / CHUNKS;
    int end   = ((cid + 1) * UNITS) / CHUNKS;

    int wm = wid & 3;        // M offset within tile: 0/32/64/96
    int wn = wid >> 2;       // N offset: 0/32/64/96
    int g  = lane >> 3;
    int l7 = lane & 7;
    int ra = l7 + (g & 1) * 8;
    int ua = g >> 1;
    int rb = l7 + (g >> 1) * 8;
    int ub = g & 1;

    uint32_t arel[2];
#pragma unroll
    for (int mf = 0; mf < 2; ++mf)
        arel[mf] = (uint32_t)((wm * 32 + mf * 16 + ra) * 256);
    uint32_t brow[2];
#pragma unroll
    for (int nf2 = 0; nf2 < 2; ++nf2)
        brow[nf2] = sb + PB_BH + (uint32_t)((wn * 32 + nf2 * 16 + rb) * 256);

    int u = start;
    int cur_nt = u >> 4;
    issue_B(sb, cur_nt, tid);
    issue_A(sb, PB_A0, u & 15, tid);
    CP_COMMIT();
    int parity = 0;

    while (u < end) {
        int nxt = u + 1;
        bool havenext = (nxt < end);
        bool samen = havenext && ((nxt >> 4) == cur_nt);
        if (samen) {
            issue_A(sb, parity ? PB_A0 : PB_A1, nxt & 15, tid);
            CP_COMMIT();
            CP_WAIT1();
        } else {
            CP_WAIT0();
        }
        __syncthreads();

        uint32_t abase = sb + (parity ? PB_A1 : PB_A0);

        float acc[2][4][4];
#pragma unroll
        for (int i = 0; i < 2; ++i)
#pragma unroll
            for (int j = 0; j < 4; ++j)
#pragma unroll
                for (int q = 0; q < 4; ++q) acc[i][j][q] = 0.0f;

        uint32_t fr[2][32];
        load_frags(fr[0], abase, arel, brow,
                   (uint32_t)((ua ^ l7) << 4), (uint32_t)((ub ^ l7) << 4));

#pragma unroll
        for (int k16 = 0; k16 < 8; ++k16) {
            int cb = k16 & 1;
            if (k16 < 7) {
                uint32_t uxa = (uint32_t)(((2 * (k16 + 1) + ua) ^ l7) << 4);
                uint32_t uxb = (uint32_t)(((2 * (k16 + 1) + ub) ^ l7) << 4);
                load_frags(fr[cb ^ 1], abase, arel, brow, uxa, uxb);
            }
            uint32_t* f = fr[cb];
            // Term 1: Ah * Bh
#pragma unroll
            for (int mf = 0; mf < 2; ++mf)
#pragma unroll
                for (int nf = 0; nf < 4; ++nf)
                    MMA_BF16(acc[mf][nf], f[mf*4], f[mf*4+1], f[mf*4+2], f[mf*4+3],
                             f[8 + nf*2], f[8 + nf*2 + 1]);
            // Term 2: Ah * Bl
#pragma unroll
            for (int mf = 0; mf < 2; ++mf)
#pragma unroll
                for (int nf = 0; nf < 4; ++nf)
                    MMA_BF16(acc[mf][nf], f[mf*4], f[mf*4+1], f[mf*4+2], f[mf*4+3],
                             f[16 + nf*2], f[16 + nf*2 + 1]);
            // Term 3: Al * Bh
#pragma unroll
            for (int mf = 0; mf < 2; ++mf)
#pragma unroll
                for (int nf = 0; nf < 4; ++nf)
                    MMA_BF16(acc[mf][nf], f[24 + mf*4], f[24 + mf*4+1], f[24 + mf*4+2], f[24 + mf*4+3],
                             f[8 + nf*2], f[8 + nf*2 + 1]);
        }

        // ---- epilogue: write into (B,S,V) layout ----
        {
            int mt = u & 15;
            bool fullT = (cur_nt != NTILES - 1);
            int m0 = mt * 128;
            int cbase = cur_nt * 128 + wn * 32 + (lane & 3) * 2;
#pragma unroll
            for (int mf = 0; mf < 2; ++mf) {
                int rr = m0 + wm * 32 + mf * 16 + (lane >> 2);
#pragma unroll
                for (int half = 0; half < 2; ++half) {
                    int m = rr + half * 8;
                    float* orow = out + (size_t)(m & 7) * SS * VV + (size_t)(m >> 3) * VV;
#pragma unroll
                    for (int nf = 0; nf < 4; ++nf) {
                        int c = cbase + nf * 8;
                        float v0 = acc[mf][nf][half * 2 + 0];
                        float v1 = acc[mf][nf][half * 2 + 1];
                        if (fullT) {
                            orow[c]     = v0;
                            orow[c + 1] = v1;
                        } else {
                            if (c < VV)     orow[c]     = v0;
                            if (c + 1 < VV) orow[c + 1] = v1;
                        }
                    }
                }
            }
        }
        __syncthreads();   // all reads done before buffers are refilled

        if (havenext && !samen) {
            cur_nt = nxt >> 4;
            issue_B(sb, cur_nt, tid);
            issue_A(sb, parity ? PB_A0 : PB_A1, nxt & 15, tid);
            CP_COMMIT();
        }
        parity ^= 1;
        u = nxt;
    }
}

// ---------------------------------------------------------------------------
extern "C" void kernel_launch(void* const* d_in, const int* in_sizes, int n_in,
                              void* d_out, int out_size) {
    const int*   input_ids = (const int*)  d_in[0];
    const float* emb       = (const float*)d_in[1];
    const float* layer_W   = (const float*)d_in[2];
    const float* layer_b   = (const float*)d_in[3];
    const float* layer_Wr  = (const float*)d_in[4];
    const float* layer_Wi  = (const float*)d_in[5];
    const float* out_w     = (const float*)d_in[6];
    float* out = (float*)d_out;

    const int smem_layers = (2 * RES + BB * DD + 2 * BB * NN + 2 * DD * 36) * sizeof(float);
    cudaFuncSetAttribute(k_layers,    cudaFuncAttributeMaxDynamicSharedMemorySize, smem_layers);
    cudaFuncSetAttribute(k_logits_wl, cudaFuncAttributeMaxDynamicSharedMemorySize, (int)SMEM_PIPE);

    k_tables<<<(RES + 255) / 256, 256>>>();
    k_recur<<<BB, DD>>>(input_ids, emb, out);
    k_split_w<<<(WROWS * 32) / 256, 256>>>(out_w);   // independent of recur/layers
    k_layers<<<SS, 512, smem_layers>>>(layer_W, layer_b, layer_Wr, layer_Wi);
    k_split_x<<<(SS * BB * 32) / 256, 256>>>();

    k_logits_wl<<<CHUNKS, 512, SMEM_PIPE>>>(out);
}

// round 10
// speedup vs baseline: 1.1226x; 1.1226x over previous
#include <cuda_runtime.h>
#include <cuda_bf16.h>
#include <math.h>
#include <stdint.h>

#define RES   4096
#define DD    128
#define NN    256
#define BB    8
#define SS    256
#define VV    50257
#define LL    2
#define WROWS 50304          // 393 * 128, padded vocab rows
#define NTILES 393
#define MTILES 16
#define UNITS  (NTILES * MTILES)   // 6288
#define CHUNKS 444                 // 148 * 3 -> exactly 3 waves

// Constants matching the reference's fp32 casts of python doubles
#define PHIF   ((float)1.6180339887498948482045868343656381177203)
#define STEPF  ((float)(6.2831853071795864769252867665590 / 4096.0))
#define SCALEF ((float)(4096.0 / 6.2831853071795864769252867665590))

// Scratch (no allocation allowed)
__device__ float g_sin[RES];
__device__ float g_cos[RES];
__device__ float g_X[SS * BB * DD];   // rows m = t*8 + b, 128 cols

// Pre-split bf16 hi/lo planes (row-major: row*128 bf16 = 256B rows)
__device__ __align__(16) __nv_bfloat16 g_Wh[WROWS * DD];
__device__ __align__(16) __nv_bfloat16 g_Wl[WROWS * DD];
__device__ __align__(16) __nv_bfloat16 g_Xh[SS * BB * DD];
__device__ __align__(16) __nv_bfloat16 g_Xl[SS * BB * DD];

// ===========================================================================
// Helpers
// ===========================================================================
__device__ __forceinline__ uint32_t smem_u32(const void* p) {
    uint32_t a;
    asm("{ .reg .u64 t; cvta.to.shared.u64 t, %1; cvt.u32.u64 %0, t; }"
        : "=r"(a) : "l"(p));
    return a;
}

__device__ __forceinline__ uint32_t pk(__nv_bfloat16 a, __nv_bfloat16 b) {
    uint16_t ua = *(uint16_t*)&a, ub = *(uint16_t*)&b;
    return (uint32_t)ua | ((uint32_t)ub << 16);
}

#define LDMATRIX_X4(r0, r1, r2, r3, addr)                                     \
    asm volatile("ldmatrix.sync.aligned.m8n8.x4.shared.b16 {%0,%1,%2,%3}, [%4];" \
        : "=r"(r0), "=r"(r1), "=r"(r2), "=r"(r3) : "r"(addr))

#define MMA_BF16(c, a0, a1, a2, a3, b0, b1)                                   \
    asm volatile("mma.sync.aligned.m16n8k16.row.col.f32.bf16.bf16.f32 "       \
        "{%0,%1,%2,%3}, {%4,%5,%6,%7}, {%8,%9}, {%0,%1,%2,%3};"               \
        : "+f"((c)[0]), "+f"((c)[1]), "+f"((c)[2]), "+f"((c)[3])              \
        : "r"(a0), "r"(a1), "r"(a2), "r"(a3), "r"(b0), "r"(b1))

#define CP_ASYNC16(smaddr, gptr)                                              \
    asm volatile("cp.async.cg.shared.global [%0], [%1], 16;"                  \
        :: "r"(smaddr), "l"(gptr))
#define CP_COMMIT() asm volatile("cp.async.commit_group;" ::: "memory")
#define CP_WAIT0()  asm volatile("cp.async.wait_group 0;" ::: "memory")
#define CP_WAIT1()  asm volatile("cp.async.wait_group 1;" ::: "memory")
#define GBAR(id)    asm volatile("bar.sync %0, 256;" :: "r"(id) : "memory")

// ---------------------------------------------------------------------------
// Kernel 0: build sin/cos tables exactly like the reference
// ---------------------------------------------------------------------------
__global__ void k_tables() {
    int i = blockIdx.x * blockDim.x + threadIdx.x;
    if (i < RES) {
        float a = __fmul_rn((float)i, STEPF);
        g_sin[i] = sinf(a);
        g_cos[i] = cosf(a);
    }
}

// ---------------------------------------------------------------------------
// Kernel 1: elementwise recurrence over t (bit-exact path, unchanged)
// ---------------------------------------------------------------------------
__global__ void k_recur(const int* __restrict__ ids,
                        const float* __restrict__ emb,
                        float* __restrict__ out) {
    __shared__ float s_sin[RES];
    __shared__ float s_cos[RES];
    __shared__ int   s_ids[SS];

    int b = blockIdx.x;
    int d = threadIdx.x;   // 128 threads

    for (int i = d; i < RES; i += 128) { s_sin[i] = g_sin[i]; s_cos[i] = g_cos[i]; }
    for (int i = d; i < SS;  i += 128) s_ids[i] = ids[b * SS + i];
    __syncthreads();

    float hr = 0.0f, hi = 0.0f;

    for (int t0 = 0; t0 < SS; t0 += 8) {
        float wv[8], bv[8];
#pragma unroll
        for (int j = 0; j < 8; ++j) {
            const float* e = emb + (size_t)s_ids[t0 + j] * (2 * DD);
            wv[j] = e[d];
            bv[j] = e[DD + d];
        }
#pragma unroll
        for (int j = 0; j < 8; ++j) {
            int   t     = t0 + j;
            float tphi  = __fmul_rn((float)t, PHIF);
            float num   = __fadd_rn(hr, hi);
            float den   = __fadd_rn(1.0f, fabsf(wv[j]));
            float theta = __fadd_rn(__fadd_rn(__fdiv_rn(num, den), bv[j]), tphi);
            int   idx   = __float2int_rn(__fmul_rn(theta, SCALEF)) & (RES - 1);
            hi = s_sin[idx];
            hr = s_cos[idx];
            g_X[(size_t)t * (BB * DD) + b * DD + d] = __fadd_rn(hr, hi);
        }
    }

    size_t base = (size_t)BB * SS * VV;
    out[base + b * DD + d]            = hr;  // h_real
    out[base + BB * DD + b * DD + d]  = hi;  // h_imag
}

// ---------------------------------------------------------------------------
// Kernel 2: the two MLP layers (reverted to the measured-78us 256-thr version)
// ---------------------------------------------------------------------------
__global__ void k_layers(const float* __restrict__ W,
                         const float* __restrict__ bias,
                         const float* __restrict__ Wr,
                         const float* __restrict__ Wi) {
    extern __shared__ float sm[];
    float* s_sin = sm;                  // 4096
    float* s_cos = s_sin + RES;         // 4096
    float* s_x   = s_cos + RES;         // 1024  (8 x 128)
    float* s_cs  = s_x + BB * DD;       // 2048  (8 x 256)
    float* s_sn  = s_cs + BB * NN;      // 2048
    float* s_wr  = s_sn + BB * NN;      // 128*36
    float* s_wi  = s_wr + DD * 36;      // 128*36

    int tid = threadIdx.x;
    int t   = blockIdx.x;

    for (int i = tid; i < RES; i += 256) { s_sin[i] = g_sin[i]; s_cos[i] = g_cos[i]; }
    float* gx = g_X + (size_t)t * (BB * DD);
    for (int i = tid; i < BB * DD; i += 256) s_x[i] = gx[i];
    __syncthreads();

    float tphi = __fmul_rn((float)t, PHIF);
    int n    = tid;
    int dcol = tid & 127;
    int bhi  = tid >> 7;   // 0 or 1

    for (int layer = 0; layer < LL; ++layer) {
        const float4* Wn = (const float4*)(W + ((size_t)layer * NN + n) * DD);
        const float4* x4 = (const float4*)s_x;
        float acc[8];
#pragma unroll
        for (int bb = 0; bb < 8; ++bb) acc[bb] = 0.0f;
#pragma unroll 8
        for (int q = 0; q < 32; ++q) {
            float4 w = Wn[q];
#pragma unroll
            for (int bb = 0; bb < 8; ++bb) {
                float4 xv = x4[bb * 32 + q];
                acc[bb] += w.x * xv.x + w.y * xv.y + w.z * xv.z + w.w * xv.w;
            }
        }
        float bsn = bias[layer * NN + n];
#pragma unroll
        for (int bb = 0; bb < 8; ++bb) {
            float th  = acc[bb] + bsn + tphi;
            int   idx = __float2int_rn(__fmul_rn(th, SCALEF)) & (RES - 1);
            s_sn[bb * NN + n] = s_sin[idx];
            s_cs[bb * NN + n] = s_cos[idx];
        }
        __syncthreads();

        float o[4] = {0.0f, 0.0f, 0.0f, 0.0f};
        const float* WrL = Wr + (size_t)layer * DD * NN;
        const float* WiL = Wi + (size_t)layer * DD * NN;
        for (int n0 = 0; n0 < NN; n0 += 32) {
#pragma unroll
            for (int l2 = 0; l2 < 16; ++l2) {
                int f  = tid + 256 * l2;   // 0..4095
                int dd = f >> 5, nn2 = f & 31;
                s_wr[dd * 36 + nn2] = WrL[dd * NN + n0 + nn2];
                s_wi[dd * 36 + nn2] = WiL[dd * NN + n0 + nn2];
            }
            __syncthreads();
            const float4* wr4 = (const float4*)(s_wr + dcol * 36);
            const float4* wi4 = (const float4*)(s_wi + dcol * 36);
#pragma unroll
            for (int q = 0; q < 8; ++q) {
                float4 wr = wr4[q];
                float4 wi = wi4[q];
#pragma unroll
                for (int p = 0; p < 4; ++p) {
                    int bb = bhi + 2 * p;
                    float4 cs = ((const float4*)(s_cs + bb * NN + n0))[q];
                    float4 sn = ((const float4*)(s_sn + bb * NN + n0))[q];
                    o[p] += cs.x * wr.x + cs.y * wr.y + cs.z * wr.z + cs.w * wr.w
                          + sn.x * wi.x + sn.y * wi.y + sn.z * wi.z + sn.w * wi.w;
                }
            }
            __syncthreads();
        }
#pragma unroll
        for (int p = 0; p < 4; ++p) {
            int bb = bhi + 2 * p;
            float ov = o[p];
            float sv = ov / (1.0f + expf(-ov));   // o * sigmoid(o)
            s_x[bb * DD + dcol] += sv;
        }
        __syncthreads();
    }

    for (int i = tid; i < BB * DD; i += 256) gx[i] = s_x[i];
}

// ---------------------------------------------------------------------------
// Split kernels: fp32 -> bf16 hi/lo planes, row-major (cp.async-ready).
// ---------------------------------------------------------------------------
__device__ __forceinline__ void split4(float4 v, uint2& hp, uint2& lp) {
    __nv_bfloat16 h0 = __float2bfloat16(v.x);
    __nv_bfloat16 h1 = __float2bfloat16(v.y);
    __nv_bfloat16 h2 = __float2bfloat16(v.z);
    __nv_bfloat16 h3 = __float2bfloat16(v.w);
    __nv_bfloat16 l0 = __float2bfloat16(v.x - __bfloat162float(h0));
    __nv_bfloat16 l1 = __float2bfloat16(v.y - __bfloat162float(h1));
    __nv_bfloat16 l2 = __float2bfloat16(v.z - __bfloat162float(h2));
    __nv_bfloat16 l3 = __float2bfloat16(v.w - __bfloat162float(h3));
    hp = make_uint2(pk(h0, h1), pk(h2, h3));
    lp = make_uint2(pk(l0, l1), pk(l2, l3));
}

__global__ void k_split_w(const float* __restrict__ Wv) {
    int f = blockIdx.x * blockDim.x + threadIdx.x;   // 0 .. WROWS*32-1
    int r = f >> 5, kq = f & 31;
    float4 v = make_float4(0.f, 0.f, 0.f, 0.f);
    if (r < VV) v = ((const float4*)Wv)[(size_t)r * 32 + kq];
    uint2 hp, lp;
    split4(v, hp, lp);
    ((uint2*)g_Wh)[f] = hp;
    ((uint2*)g_Wl)[f] = lp;
}

__global__ void k_split_x() {
    int f = blockIdx.x * blockDim.x + threadIdx.x;   // 0 .. 2048*32-1
    float4 v = ((const float4*)g_X)[f];
    uint2 hp, lp;
    split4(v, hp, lp);
    ((uint2*)g_Xh)[f] = hp;
    ((uint2*)g_Xl)[f] = lp;
}

// ---------------------------------------------------------------------------
// Kernel 3: work-list logits GEMM with TWO independent 8-warp groups.
//   444 CTAs (3 waves) x 512 thr. Unit = (nt, mt): 128x128 output tile.
//   Group g handles rows [g*64, g*64+64) of every tile with its OWN
//   double-buffered 32KB A planes and named-barrier sync -> group0's
//   epilogue overlaps group1's MMAs. B (64KB) is CTA-shared, reloaded only
//   at nt boundaries (full __syncthreads, uniform condition).
// smem: BH 32K | BL 32K | G0A0 32K | G0A1 32K | G1A0 32K | G1A1 32K = 192K
// ---------------------------------------------------------------------------
#define PB_BH 0u
#define PB_BL 32768u
#define PB_A  65536u
#define SMEM_PIPE 196608u

__device__ __forceinline__ void issue_B(uint32_t sb, int nt, int tid) {
    const char* gWh = (const char*)g_Wh;
    const char* gWl = (const char*)g_Wl;
#pragma unroll
    for (int i = 0; i < 4; ++i) {
        int f = tid + 512 * i;            // 0..2047
        int r = f >> 4, u = f & 15;
        uint32_t so = (uint32_t)(r * 256 + ((u ^ (r & 7)) << 4));
        size_t   go = (size_t)(nt * 128 + r) * 256 + u * 16;
        CP_ASYNC16(sb + PB_BH + so, gWh + go);
        CP_ASYNC16(sb + PB_BL + so, gWl + go);
    }
}

// Load 64 rows (this group's half of an M-tile) into a 32KB buffer.
__device__ __forceinline__ void issue_Ag(uint32_t abuf, int mt, int grp, int gtid) {
    const char* gXh = (const char*)g_Xh;
    const char* gXl = (const char*)g_Xl;
#pragma unroll
    for (int i = 0; i < 4; ++i) {
        int f = gtid + 256 * i;           // 0..1023
        int r = f >> 4, u = f & 15;       // r: 0..63
        uint32_t so = (uint32_t)(r * 256 + ((u ^ (r & 7)) << 4));
        size_t   go = (size_t)(mt * 128 + grp * 64 + r) * 256 + u * 16;
        CP_ASYNC16(abuf + so, gXh + go);
        CP_ASYNC16(abuf + 16384u + so, gXl + go);
    }
}

__global__ void __launch_bounds__(512, 1)
k_logits_wg(float* __restrict__ out) {
    extern __shared__ char smc[];
    uint32_t sb = smem_u32(smc);

    int tid  = threadIdx.x;
    int lane = tid & 31;
    int wid  = tid >> 5;
    int grp  = wid >> 3;           // 0 or 1
    int gwid = wid & 7;            // warp within group
    int gtid = tid & 255;
    int bar  = 1 + grp;
    int cid  = blockIdx.x;

    int start = (cid * UNITS) / CHUNKS;
    int end   = ((cid + 1) * UNITS) / CHUNKS;

    int wm = gwid & 1;             // M offset within 64-row half: 0/32
    int wn = gwid >> 1;            // N offset: 0/32/64/96
    int g  = lane >> 3;
    int l7 = lane & 7;
    int ra = l7 + (g & 1) * 8;
    int ua = g >> 1;
    int rb = l7 + (g >> 1) * 8;
    int ub = g & 1;

    // A buffer bases for this group (hi plane; lo at +16384)
    uint32_t abuf0 = sb + PB_A + (uint32_t)grp * 65536u;
    uint32_t abuf1 = abuf0 + 32768u;

    uint32_t arel[2];
#pragma unroll
    for (int mf = 0; mf < 2; ++mf)
        arel[mf] = (uint32_t)((wm * 32 + mf * 16 + ra) * 256);
    uint32_t brow[2];
#pragma unroll
    for (int nf2 = 0; nf2 < 2; ++nf2)
        brow[nf2] = sb + PB_BH + (uint32_t)((wn * 32 + nf2 * 16 + rb) * 256);

    int u = start;
    int cur_nt = u >> 4;
    issue_B(sb, cur_nt, tid);
    issue_Ag(abuf0, u & 15, grp, gtid);
    CP_COMMIT();
    int parity = 0;
    bool freshB = true;

    while (u < end) {
        int nxt = u + 1;
        bool havenext = (nxt < end);
        bool samen = havenext && ((nxt >> 4) == cur_nt);
        if (samen) {
            issue_Ag(parity ? abuf0 : abuf1, nxt & 15, grp, gtid);
            CP_COMMIT();
            CP_WAIT1();
        } else {
            CP_WAIT0();
        }
        if (freshB) { __syncthreads(); freshB = false; }
        else        { GBAR(bar); }

        uint32_t abase = parity ? abuf1 : abuf0;

        float acc[2][4][4];
#pragma unroll
        for (int i = 0; i < 2; ++i)
#pragma unroll
            for (int j = 0; j < 4; ++j)
#pragma unroll
                for (int q = 0; q < 4; ++q) acc[i][j][q] = 0.0f;

#pragma unroll
        for (int k16 = 0; k16 < 8; ++k16) {
            uint32_t uxa = (uint32_t)(((2 * k16 + ua) ^ l7) << 4);
            uint32_t uxb = (uint32_t)(((2 * k16 + ub) ^ l7) << 4);

            uint32_t aH[2][4], bH[2][4];
#pragma unroll
            for (int mf = 0; mf < 2; ++mf)
                LDMATRIX_X4(aH[mf][0], aH[mf][1], aH[mf][2], aH[mf][3],
                            abase + arel[mf] + uxa);
#pragma unroll
            for (int nf2 = 0; nf2 < 2; ++nf2)
                LDMATRIX_X4(bH[nf2][0], bH[nf2][1], bH[nf2][2], bH[nf2][3],
                            brow[nf2] + uxb);

            // Term 1: Ah * Bh
#pragma unroll
            for (int mf = 0; mf < 2; ++mf)
#pragma unroll
                for (int nf = 0; nf < 4; ++nf)
                    MMA_BF16(acc[mf][nf], aH[mf][0], aH[mf][1], aH[mf][2], aH[mf][3],
                             bH[nf >> 1][(nf & 1) * 2], bH[nf >> 1][(nf & 1) * 2 + 1]);

            // Term 2: Ah * Bl
            {
                uint32_t bL[2][4];
#pragma unroll
                for (int nf2 = 0; nf2 < 2; ++nf2)
                    LDMATRIX_X4(bL[nf2][0], bL[nf2][1], bL[nf2][2], bL[nf2][3],
                                brow[nf2] + 32768u + uxb);
#pragma unroll
                for (int mf = 0; mf < 2; ++mf)
#pragma unroll
                    for (int nf = 0; nf < 4; ++nf)
                        MMA_BF16(acc[mf][nf], aH[mf][0], aH[mf][1], aH[mf][2], aH[mf][3],
                                 bL[nf >> 1][(nf & 1) * 2], bL[nf >> 1][(nf & 1) * 2 + 1]);
            }

            // Term 3: Al * Bh
            {
                uint32_t aL[2][4];
#pragma unroll
                for (int mf = 0; mf < 2; ++mf)
                    LDMATRIX_X4(aL[mf][0], aL[mf][1], aL[mf][2], aL[mf][3],
                                abase + 16384u + arel[mf] + uxa);
#pragma unroll
                for (int mf = 0; mf < 2; ++mf)
#pragma unroll
                    for (int nf = 0; nf < 4; ++nf)
                        MMA_BF16(acc[mf][nf], aL[mf][0], aL[mf][1], aL[mf][2], aL[mf][3],
                                 bH[nf >> 1][(nf & 1) * 2], bH[nf >> 1][(nf & 1) * 2 + 1]);
            }
        }

        // ---- epilogue: write into (B,S,V) layout ----
        {
            int mt = u & 15;
            bool fullT = (cur_nt != NTILES - 1);
            int m0 = mt * 128 + grp * 64;
            int cbase = cur_nt * 128 + wn * 32 + (lane & 3) * 2;
#pragma unroll
            for (int mf = 0; mf < 2; ++mf) {
                int rr = m0 + wm * 32 + mf * 16 + (lane >> 2);
#pragma unroll
                for (int half = 0; half < 2; ++half) {
                    int m = rr + half * 8;
                    float* orow = out + (size_t)(m & 7) * SS * VV + (size_t)(m >> 3) * VV;
#pragma unroll
                    for (int nf = 0; nf < 4; ++nf) {
                        int c = cbase + nf * 8;
                        float v0 = acc[mf][nf][half * 2 + 0];
                        float v1 = acc[mf][nf][half * 2 + 1];
                        if (fullT) {
                            orow[c]     = v0;
                            orow[c + 1] = v1;
                        } else {
                            if (c < VV)     orow[c]     = v0;
                            if (c + 1 < VV) orow[c + 1] = v1;
                        }
                    }
                }
            }
        }

        if (havenext && !samen) {
            // nt boundary: all warps (both groups) must be done with B
            __syncthreads();
            cur_nt = nxt >> 4;
            issue_B(sb, cur_nt, tid);
            issue_Ag(parity ? abuf0 : abuf1, nxt & 15, grp, gtid);
            CP_COMMIT();
            freshB = true;
        } else {
            GBAR(bar);   // group's A buffer safe to refill next iteration
        }
        parity ^= 1;
        u = nxt;
    }
}

// ---------------------------------------------------------------------------
extern "C" void kernel_launch(void* const* d_in, const int* in_sizes, int n_in,
                              void* d_out, int out_size) {
    const int*   input_ids = (const int*)  d_in[0];
    const float* emb       = (const float*)d_in[1];
    const float* layer_W   = (const float*)d_in[2];
    const float* layer_b   = (const float*)d_in[3];
    const float* layer_Wr  = (const float*)d_in[4];
    const float* layer_Wi  = (const float*)d_in[5];
    const float* out_w     = (const float*)d_in[6];
    float* out = (float*)d_out;

    const int smem_layers = (2 * RES + BB * DD + 2 * BB * NN + 2 * DD * 36) * sizeof(float);
    cudaFuncSetAttribute(k_layers,    cudaFuncAttributeMaxDynamicSharedMemorySize, smem_layers);
    cudaFuncSetAttribute(k_logits_wg, cudaFuncAttributeMaxDynamicSharedMemorySize, (int)SMEM_PIPE);

    k_tables<<<(RES + 255) / 256, 256>>>();
    k_recur<<<BB, DD>>>(input_ids, emb, out);
    k_split_w<<<(WROWS * 32) / 256, 256>>>(out_w);   // independent of recur/layers
    k_layers<<<SS, 256, smem_layers>>>(layer_W, layer_b, layer_Wr, layer_Wi);
    k_split_x<<<(SS * BB * 32) / 256, 256>>>();

    k_logits_wg<<<CHUNKS, 512, SMEM_PIPE>>>(out);
}